// round 16
// baseline (speedup 1.0000x reference)
#include <cuda_runtime.h>
#include <cuda_fp16.h>
#include <math.h>

// Problem constants
#define B_SZ   64
#define BG     32            // batch-group size for k_uhat (W L2-reuse)
#define I_CAPS 2048
#define D_DIM  16
#define JK     512
#define NCHUNK 32            // pass chunks (64 i per CTA)

// Scratch (device globals — allocation-free rule)
__device__ __half g_uhat[(size_t)B_SZ * I_CAPS * JK];     // 134 MB, [b][i][jk]
__device__ float  g_part[NCHUNK * B_SZ * JK];             // 4 MB partials
__device__ float  g_out1[B_SZ * JK];
__device__ float  g_outc[B_SZ * JK];

// ---- packed f32x2 helpers (FFMA2 only reachable via PTX) ------------------
__device__ __forceinline__ void fma2(unsigned long long& d,
                                     unsigned long long a, unsigned long long b) {
    asm("fma.rn.f32x2 %0, %1, %2, %0;" : "+l"(d) : "l"(a), "l"(b));
}
__device__ __forceinline__ float2 up2(unsigned long long v) {
    float2 r;
    asm("mov.b64 {%0,%1}, %2;" : "=f"(r.x), "=f"(r.y) : "l"(v));
    return r;
}

// ---- warp allreduce-add (redux.f32 unsupported on sm_103) ------------------
__device__ __forceinline__ float warp_sum(float v) {
    v += __shfl_xor_sync(0xffffffffu, v, 1);
    v += __shfl_xor_sync(0xffffffffu, v, 2);
    v += __shfl_xor_sync(0xffffffffu, v, 4);
    v += __shfl_xor_sync(0xffffffffu, v, 8);
    v += __shfl_xor_sync(0xffffffffu, v, 16);
    return v;
}

// ---- 32B streaming load for W only (proven fine in k_uhat) -----------------
struct U8 { uint4 a, b; };
__device__ __forceinline__ U8 ldg_v8_stream(const void* p) {
    U8 v;
    asm("ld.global.nc.L2::evict_first.v4.b64 {%0,%1,%2,%3}, [%4];"
        : "=l"(*(unsigned long long*)&v.a.x),
          "=l"(*(unsigned long long*)&v.a.z),
          "=l"(*(unsigned long long*)&v.b.x),
          "=l"(*(unsigned long long*)&v.b.z) : "l"(p));
    return v;
}

// ---------------------------------------------------------------------------
// K1 (grouped, round-9 proven schedule): u_hat[b0+lb,i,jk] = x @ W[i], fp16.
// One block (128 thr) per i; W[i] in smem reused across 32 lb; x (v,v)-dup so
// the f32x2 multiplier is one LDS.64 broadcast. Two launches (b0 = 0, 32).
// ---------------------------------------------------------------------------
__global__ void __launch_bounds__(128)
k_uhat(const float* __restrict__ x, const float* __restrict__ W, int b_base) {
    __shared__ float  Wsh[8192];
    __shared__ float2 xdup[BG][D_DIM];

    const int i = blockIdx.x;
    const int t = threadIdx.x;

    {
        const char* Wg = reinterpret_cast<const char*>(W + (size_t)i * 8192);
        U8* Ws8 = reinterpret_cast<U8*>(Wsh);
        #pragma unroll
        for (int r = 0; r < 8; r++)
            Ws8[t + 128 * r] = ldg_v8_stream(Wg + 32 * (t + 128 * r));
    }
    {
        #pragma unroll
        for (int r = 0; r < 4; r++) {
            const int e = t + 128 * r;
            const int lb = e >> 4, d = e & 15;
            const float v = x[((size_t)(b_base + lb) * I_CAPS + i) * D_DIM + d];
            xdup[lb][d] = make_float2(v, v);
        }
    }
    __syncthreads();

    const int j  = t >> 2;
    const int k0 = (t & 3) * 4;

    unsigned long long wA[D_DIM], wB[D_DIM];
    #pragma unroll
    for (int d = 0; d < D_DIM; d++) {
        const float* wp = &Wsh[j * 256 + d * 16 + k0];
        wA[d] = *reinterpret_cast<const unsigned long long*>(wp);
        wB[d] = *reinterpret_cast<const unsigned long long*>(wp + 2);
    }

    __half* outp = g_uhat + ((size_t)b_base * I_CAPS + (size_t)i) * JK + 4 * t;
    #pragma unroll 2
    for (int lb = 0; lb < BG; lb++) {
        unsigned long long u01 = 0ull, u23 = 0ull;
        #pragma unroll
        for (int d = 0; d < D_DIM; d++) {
            const unsigned long long xx =
                *reinterpret_cast<const unsigned long long*>(&xdup[lb][d]);
            fma2(u01, xx, wA[d]);
            fma2(u23, xx, wB[d]);
        }
        const float2 a = up2(u01), c = up2(u23);
        __half2 h0 = __float22half2_rn(make_float2(a.x, a.y));
        __half2 h1 = __float22half2_rn(make_float2(c.x, c.y));
        uint2 st;
        st.x = *reinterpret_cast<unsigned int*>(&h0);
        st.y = *reinterpret_cast<unsigned int*>(&h1);
        *reinterpret_cast<uint2*>(outp + (size_t)lb * ((size_t)I_CAPS * JK)) = st;
    }
}

// ---------------------------------------------------------------------------
// Routing pass — the round-4 measured-fastest configuration verbatim:
// full batch, grid (32,64)=2048 CTAs, 4 warps x 16 i, lane l owns j=l all k,
// TWO independent 16B LDG.128 per i (the 32B LDG.256 variant measured
// 3.7 TB/s vs 4.67 TB/s for this form — more loads = deeper L1tex queue).
// MODE 1: lane-local logit dot; softmax over j = 5-shuffle z-allreduce.
// ---------------------------------------------------------------------------
template <int MODE>
__global__ void __launch_bounds__(128, 8)
k_pass(int which_out) {
    __shared__ float red[4][16 * 33];

    const int b = blockIdx.y;
    const int t = threadIdx.x;
    const int w = t >> 5;
    const int l = t & 31;

    float o[16];
    if (MODE == 1) {
        const float* outv = (which_out == 0) ? g_out1 : g_outc;
        const float4* op = reinterpret_cast<const float4*>(
            outv + (size_t)b * JK + l * 16);
        #pragma unroll
        for (int q = 0; q < 4; q++) {
            float4 v = op[q];
            o[q * 4] = v.x; o[q * 4 + 1] = v.y; o[q * 4 + 2] = v.z; o[q * 4 + 3] = v.w;
        }
    }

    float acc[16];
    #pragma unroll
    for (int m = 0; m < 16; m++) acc[m] = 0.f;

    const __half* base = g_uhat + ((size_t)b * I_CAPS
                       + (size_t)(blockIdx.x * 64 + w * 16)) * JK;
    const uint4* p = reinterpret_cast<const uint4*>(base) + 2 * l;

    #pragma unroll
    for (int ii = 0; ii < 16; ii++) {
        const uint4 a0 = p[ii * 64];
        const uint4 a1 = p[ii * 64 + 1];

        float u[16];
        {
            const unsigned int* pa = &a0.x;
            const unsigned int* pb = &a1.x;
            #pragma unroll
            for (int h = 0; h < 4; h++) {
                float2 va = __half22float2(*reinterpret_cast<const __half2*>(&pa[h]));
                u[h * 2] = va.x; u[h * 2 + 1] = va.y;
                float2 vb = __half22float2(*reinterpret_cast<const __half2*>(&pb[h]));
                u[8 + h * 2] = vb.x; u[8 + h * 2 + 1] = vb.y;
            }
        }

        if (MODE == 1) {
            float lg = 0.f;
            #pragma unroll
            for (int m = 0; m < 16; m++) lg = fmaf(u[m], o[m], lg);
            const float e = __expf(lg);
            const float z = warp_sum(e);
            const float c = __fdividef(e, z);
            #pragma unroll
            for (int m = 0; m < 16; m++) acc[m] = fmaf(c, u[m], acc[m]);
        } else {
            #pragma unroll
            for (int m = 0; m < 16; m++) acc[m] += u[m];
        }
    }

    #pragma unroll
    for (int m = 0; m < 16; m++) red[w][m * 33 + l] = acc[m];
    __syncthreads();

    const int lo = t >> 2;
    const int mo = (t & 3) * 4;
    float4 s;
    float* sp = &s.x;
    #pragma unroll
    for (int c = 0; c < 4; c++) {
        float v = 0.f;
        #pragma unroll
        for (int w2 = 0; w2 < 4; w2++) v += red[w2][(mo + c) * 33 + lo];
        sp[c] = v;
    }
    *reinterpret_cast<float4*>(
        &g_part[((size_t)blockIdx.x * B_SZ + b) * JK + 4 * t]) = s;
}

// ---------------------------------------------------------------------------
// Squash, 4x parallelized: grid (64, 4), 128 thr; block owns jk-quarter
// [128*blockIdx.y, +128). k=16 shuffle reduction unchanged (same-j lanes share
// a 16-lane half). mode 0 -> g_out1 ; 1 -> g_outc = g_out1 + squash ; 2 -> out.
// ---------------------------------------------------------------------------
__global__ void __launch_bounds__(128)
k_squash(int mode, float* __restrict__ dout) {
    const int b = blockIdx.x;
    const int jk = blockIdx.y * 128 + threadIdx.x;

    float v = 0.f;
    #pragma unroll
    for (int c = 0; c < NCHUNK; c++) v += g_part[((size_t)c * B_SZ + b) * JK + jk];
    if (mode == 0) v *= (1.f / 32.f);

    float sq = v * v;
    sq += __shfl_xor_sync(0xffffffffu, sq, 1);
    sq += __shfl_xor_sync(0xffffffffu, sq, 2);
    sq += __shfl_xor_sync(0xffffffffu, sq, 4);
    sq += __shfl_xor_sync(0xffffffffu, sq, 8);

    const float scale = sq / ((1.f + sq) * sqrtf(sq + 1e-7f));
    const float o = scale * v;

    if (mode == 0)      g_out1[(size_t)b * JK + jk] = o;
    else if (mode == 1) g_outc[(size_t)b * JK + jk] = g_out1[(size_t)b * JK + jk] + o;
    else                dout[(size_t)b * JK + jk] = o;
}

// ---------------------------------------------------------------------------
extern "C" void kernel_launch(void* const* d_in, const int* in_sizes, int n_in,
                              void* d_out, int out_size) {
    const float* x = (const float*)d_in[0];
    const float* W = (const float*)d_in[1];
    if (n_in >= 2 && in_sizes[0] == 16777216 && in_sizes[1] == 2097152) {
        const float* tmp = x; x = W; W = tmp;
    }
    float* out = (float*)d_out;

    // k_uhat grouped (W L2-reuse across the two launches)
    k_uhat<<<I_CAPS, 128>>>(x, W, 0);
    k_uhat<<<I_CAPS, 128>>>(x, W, BG);

    // Routing rounds at full batch with 2x16B loads (measured 4.67 TB/s)
    dim3 pg(NCHUNK, B_SZ);
    dim3 sg(B_SZ, 4);
    k_pass<0><<<pg, 128>>>(0);           // round 1
    k_squash<<<sg, 128>>>(0, nullptr);
    k_pass<1><<<pg, 128>>>(0);           // round 2
    k_squash<<<sg, 128>>>(1, nullptr);
    k_pass<1><<<pg, 128>>>(1);           // round 3
    k_squash<<<sg, 128>>>(2, out);
}

// round 17
// speedup vs baseline: 1.1767x; 1.1767x over previous
#include <cuda_runtime.h>
#include <cuda_fp16.h>
#include <math.h>

// Problem constants
#define B_SZ   64
#define BG     32            // batch-group size
#define NGROUP 2
#define I_CAPS 2048
#define D_DIM  16
#define JK     512
#define NCHUNK 32            // i-chunks (64 i per pass-CTA)

// Scratch (device globals — allocation-free rule)
__device__ __half g_uhat[(size_t)BG * I_CAPS * JK];       // 67 MB group slice
__device__ float  g_part[NCHUNK * BG * JK];               // 2 MB partials
__device__ float  g_out1[B_SZ * JK];
__device__ float  g_outc[B_SZ * JK];

// ---- packed f32x2 helpers (FFMA2 only reachable via PTX) ------------------
__device__ __forceinline__ void fma2(unsigned long long& d,
                                     unsigned long long a, unsigned long long b) {
    asm("fma.rn.f32x2 %0, %1, %2, %0;" : "+l"(d) : "l"(a), "l"(b));
}
__device__ __forceinline__ float2 up2(unsigned long long v) {
    float2 r;
    asm("mov.b64 {%0,%1}, %2;" : "=f"(r.x), "=f"(r.y) : "l"(v));
    return r;
}

// ---- warp allreduce-add -----------------------------------------------------
__device__ __forceinline__ float warp_sum(float v) {
    v += __shfl_xor_sync(0xffffffffu, v, 1);
    v += __shfl_xor_sync(0xffffffffu, v, 2);
    v += __shfl_xor_sync(0xffffffffu, v, 4);
    v += __shfl_xor_sync(0xffffffffu, v, 8);
    v += __shfl_xor_sync(0xffffffffu, v, 16);
    return v;
}

// ---- 32B loads (.v4.b64) ----------------------------------------------------
struct U8 { uint4 a, b; };

__device__ __forceinline__ U8 ldg_v8(const void* p) {
    U8 v;
    asm("ld.global.v4.b64 {%0,%1,%2,%3}, [%4];"
        : "=l"(*(unsigned long long*)&v.a.x),
          "=l"(*(unsigned long long*)&v.a.z),
          "=l"(*(unsigned long long*)&v.b.x),
          "=l"(*(unsigned long long*)&v.b.z) : "l"(p));
    return v;
}
__device__ __forceinline__ U8 ldg_v8_ef(const void* p) {          // dead data
    U8 v;
    asm("ld.global.L2::evict_first.v4.b64 {%0,%1,%2,%3}, [%4];"
        : "=l"(*(unsigned long long*)&v.a.x),
          "=l"(*(unsigned long long*)&v.a.z),
          "=l"(*(unsigned long long*)&v.b.x),
          "=l"(*(unsigned long long*)&v.b.z) : "l"(p));
    return v;
}
__device__ __forceinline__ U8 ldg_v8_stream(const void* p) {      // W: stream
    U8 v;
    asm("ld.global.nc.L2::evict_first.v4.b64 {%0,%1,%2,%3}, [%4];"
        : "=l"(*(unsigned long long*)&v.a.x),
          "=l"(*(unsigned long long*)&v.a.z),
          "=l"(*(unsigned long long*)&v.b.x),
          "=l"(*(unsigned long long*)&v.b.z) : "l"(p));
    return v;
}

// ---------------------------------------------------------------------------
// K1 (per group, round-9 proven): u_hat[lb,i,jk] = x[b0+lb,i,:] @ W[i], fp16.
// One block (128 thr) per i. W[i] in smem, reused across 32 lb; x (v,v)-dup.
// ---------------------------------------------------------------------------
__global__ void __launch_bounds__(128)
k_uhat(const float* __restrict__ x, const float* __restrict__ W, int b_base) {
    __shared__ float  Wsh[8192];
    __shared__ float2 xdup[BG][D_DIM];

    const int i = blockIdx.x;
    const int t = threadIdx.x;

    {
        const char* Wg = reinterpret_cast<const char*>(W + (size_t)i * 8192);
        U8* Ws8 = reinterpret_cast<U8*>(Wsh);
        #pragma unroll
        for (int r = 0; r < 8; r++)
            Ws8[t + 128 * r] = ldg_v8_stream(Wg + 32 * (t + 128 * r));
    }
    {
        #pragma unroll
        for (int r = 0; r < 4; r++) {
            const int e = t + 128 * r;
            const int lb = e >> 4, d = e & 15;
            const float v = x[((size_t)(b_base + lb) * I_CAPS + i) * D_DIM + d];
            xdup[lb][d] = make_float2(v, v);
        }
    }
    __syncthreads();

    const int j  = t >> 2;
    const int k0 = (t & 3) * 4;

    unsigned long long wA[D_DIM], wB[D_DIM];
    #pragma unroll
    for (int d = 0; d < D_DIM; d++) {
        const float* wp = &Wsh[j * 256 + d * 16 + k0];
        wA[d] = *reinterpret_cast<const unsigned long long*>(wp);
        wB[d] = *reinterpret_cast<const unsigned long long*>(wp + 2);
    }

    __half* outp = g_uhat + (size_t)i * JK + 4 * t;
    #pragma unroll 2
    for (int lb = 0; lb < BG; lb++) {
        unsigned long long u01 = 0ull, u23 = 0ull;
        #pragma unroll
        for (int d = 0; d < D_DIM; d++) {
            const unsigned long long xx =
                *reinterpret_cast<const unsigned long long*>(&xdup[lb][d]);
            fma2(u01, xx, wA[d]);
            fma2(u23, xx, wB[d]);
        }
        const float2 a = up2(u01), c = up2(u23);
        __half2 h0 = __float22half2_rn(make_float2(a.x, a.y));
        __half2 h1 = __float22half2_rn(make_float2(c.x, c.y));
        uint2 st;
        st.x = *reinterpret_cast<unsigned int*>(&h0);
        st.y = *reinterpret_cast<unsigned int*>(&h1);
        *reinterpret_cast<uint2*>(outp + (size_t)lb * ((size_t)I_CAPS * JK)) = st;
    }
}

// ---------------------------------------------------------------------------
// Routing pass (round-9 structure + dual-i interleave). blockIdx.y = lb,
// blockIdx.x = chunk of 64 i. 4 warps x 16 i; each iteration handles i and
// i+8 with two INDEPENDENT 32B loads and two independent softmax chains —
// doubles per-warp MLP and halves serial-chain density (round-9 profile:
// DRAM 48%, issue 30% -> latency-bound). KEEP=0 (final pass): evict_first.
// ---------------------------------------------------------------------------
template <int MODE, int KEEP>
__global__ void __launch_bounds__(128, 6)
k_pass(int which_out, int b_base) {
    __shared__ float red[4][16 * 33];

    const int lb = blockIdx.y;
    const int t = threadIdx.x;
    const int w = t >> 5;
    const int l = t & 31;

    float o[16];
    if (MODE == 1) {
        const float* outv = (which_out == 0) ? g_out1 : g_outc;
        const float4* op = reinterpret_cast<const float4*>(
            outv + (size_t)(b_base + lb) * JK + l * 16);
        #pragma unroll
        for (int q = 0; q < 4; q++) {
            float4 v = op[q];
            o[q * 4] = v.x; o[q * 4 + 1] = v.y; o[q * 4 + 2] = v.z; o[q * 4 + 3] = v.w;
        }
    }

    float acc[16];
    #pragma unroll
    for (int m = 0; m < 16; m++) acc[m] = 0.f;

    const __half* base = g_uhat + ((size_t)lb * I_CAPS
                       + (size_t)(blockIdx.x * 64 + w * 16)) * JK;
    const char* p = reinterpret_cast<const char*>(base) + 32 * l;

    #pragma unroll
    for (int ii = 0; ii < 8; ii++) {
        const U8 ra = KEEP ? ldg_v8(p + ii * 1024)       : ldg_v8_ef(p + ii * 1024);
        const U8 rb = KEEP ? ldg_v8(p + (ii + 8) * 1024) : ldg_v8_ef(p + (ii + 8) * 1024);

        float ua[16], ub[16];
        {
            const unsigned int* a0 = &ra.a.x;
            const unsigned int* a1 = &ra.b.x;
            const unsigned int* b0 = &rb.a.x;
            const unsigned int* b1 = &rb.b.x;
            #pragma unroll
            for (int h = 0; h < 4; h++) {
                float2 v;
                v = __half22float2(*reinterpret_cast<const __half2*>(&a0[h]));
                ua[h * 2] = v.x; ua[h * 2 + 1] = v.y;
                v = __half22float2(*reinterpret_cast<const __half2*>(&a1[h]));
                ua[8 + h * 2] = v.x; ua[8 + h * 2 + 1] = v.y;
                v = __half22float2(*reinterpret_cast<const __half2*>(&b0[h]));
                ub[h * 2] = v.x; ub[h * 2 + 1] = v.y;
                v = __half22float2(*reinterpret_cast<const __half2*>(&b1[h]));
                ub[8 + h * 2] = v.x; ub[8 + h * 2 + 1] = v.y;
            }
        }

        if (MODE == 1) {
            float lga = 0.f, lgb = 0.f;
            #pragma unroll
            for (int m = 0; m < 16; m++) {
                lga = fmaf(ua[m], o[m], lga);
                lgb = fmaf(ub[m], o[m], lgb);
            }
            const float ea = __expf(lga);
            const float eb = __expf(lgb);
            // two independent z-allreduces; chains interleave in the pipeline
            float za = ea, zb = eb;
            #pragma unroll
            for (int sh = 1; sh <= 16; sh <<= 1) {
                za += __shfl_xor_sync(0xffffffffu, za, sh);
                zb += __shfl_xor_sync(0xffffffffu, zb, sh);
            }
            const float ca = __fdividef(ea, za);
            const float cb = __fdividef(eb, zb);
            #pragma unroll
            for (int m = 0; m < 16; m++) {
                acc[m] = fmaf(ca, ua[m], acc[m]);
                acc[m] = fmaf(cb, ub[m], acc[m]);
            }
        } else {
            #pragma unroll
            for (int m = 0; m < 16; m++) acc[m] += ua[m] + ub[m];
        }
    }

    #pragma unroll
    for (int m = 0; m < 16; m++) red[w][m * 33 + l] = acc[m];
    __syncthreads();

    const int lo = t >> 2;
    const int mo = (t & 3) * 4;
    float4 s;
    float* sp = &s.x;
    #pragma unroll
    for (int c = 0; c < 4; c++) {
        float v = 0.f;
        #pragma unroll
        for (int w2 = 0; w2 < 4; w2++) v += red[w2][(mo + c) * 33 + lo];
        sp[c] = v;
    }
    *reinterpret_cast<float4*>(
        &g_part[((size_t)blockIdx.x * BG + lb) * JK + 4 * t]) = s;
}

// ---------------------------------------------------------------------------
// Squash (per group): reduce 32 chunk-partials, squash per (b,j) over k=16.
// ---------------------------------------------------------------------------
__global__ void __launch_bounds__(512)
k_squash(int mode, float* __restrict__ dout, int b_base) {
    const int lb = blockIdx.x;
    const int t = threadIdx.x;
    const int b = b_base + lb;

    float v = 0.f;
    #pragma unroll
    for (int c = 0; c < NCHUNK; c++) v += g_part[((size_t)c * BG + lb) * JK + t];
    if (mode == 0) v *= (1.f / 32.f);

    float sq = v * v;
    sq += __shfl_xor_sync(0xffffffffu, sq, 1);
    sq += __shfl_xor_sync(0xffffffffu, sq, 2);
    sq += __shfl_xor_sync(0xffffffffu, sq, 4);
    sq += __shfl_xor_sync(0xffffffffu, sq, 8);

    const float scale = sq / ((1.f + sq) * sqrtf(sq + 1e-7f));
    const float o = scale * v;

    if (mode == 0)      g_out1[(size_t)b * JK + t] = o;
    else if (mode == 1) g_outc[(size_t)b * JK + t] = g_out1[(size_t)b * JK + t] + o;
    else                dout[(size_t)b * JK + t] = o;
}

// ---------------------------------------------------------------------------
extern "C" void kernel_launch(void* const* d_in, const int* in_sizes, int n_in,
                              void* d_out, int out_size) {
    const float* x = (const float*)d_in[0];
    const float* W = (const float*)d_in[1];
    if (n_in >= 2 && in_sizes[0] == 16777216 && in_sizes[1] == 2097152) {
        const float* tmp = x; x = W; W = tmp;
    }
    float* out = (float*)d_out;

    // Round-9 proven schedule: fully grouped (k_uhat -> 3 passes -> squash)
    for (int g = 0; g < NGROUP; g++) {
        const int b0 = g * BG;
        k_uhat<<<I_CAPS, 128>>>(x, W, b0);

        dim3 pg(NCHUNK, BG);
        k_pass<0, 1><<<pg, 128>>>(0, b0);        // round 1
        k_squash<<<BG, 512>>>(0, nullptr, b0);
        k_pass<1, 1><<<pg, 128>>>(0, b0);        // round 2
        k_squash<<<BG, 512>>>(1, nullptr, b0);
        k_pass<1, 0><<<pg, 128>>>(1, b0);        // round 3 (release L2)
        k_squash<<<BG, 512>>>(2, out, b0);
    }
}